// round 1
// baseline (speedup 1.0000x reference)
#include <cuda_runtime.h>

// Problem constants (fixed shapes from reference: I(16,3,512,512), T(16,256), P(3,16), Q(16,3))
#define BS        16
#define CHANS     3
#define HW        (512 * 512)        // 262144 elems per channel
#define NCH       (BS * CHANS)       // 48 channel slabs
#define PARTS     64                 // partial sums per channel
#define CHUNK     (HW / PARTS)       // 4096 floats per block
#define THREADS   256
#define KDIM      16

// Deterministic scratch: no atomics, fixed write slots.
__device__ float g_partials[NCH * PARTS];

__global__ __launch_bounds__(THREADS)
void dncm_reduce_kernel(const float* __restrict__ I) {
    const int bid  = blockIdx.x;          // 0 .. NCH*PARTS-1
    const int ch   = bid >> 6;            // /PARTS
    const int part = bid & (PARTS - 1);

    const float4* __restrict__ base =
        reinterpret_cast<const float4*>(I + (size_t)ch * HW + (size_t)part * CHUNK);

    const int t = threadIdx.x;
    // CHUNK/4 = 1024 float4, 256 threads -> 4 independent vector loads each (MLP=4)
    float4 a = base[t];
    float4 b = base[t + 256];
    float4 c = base[t + 512];
    float4 d = base[t + 768];

    float s = ((a.x + a.y) + (a.z + a.w))
            + ((b.x + b.y) + (b.z + b.w))
            + ((c.x + c.y) + (c.z + c.w))
            + ((d.x + d.y) + (d.z + d.w));

    // warp tree reduce
    #pragma unroll
    for (int off = 16; off > 0; off >>= 1)
        s += __shfl_xor_sync(0xffffffffu, s, off);

    __shared__ float smem[THREADS / 32];
    const int wid = t >> 5;
    const int lid = t & 31;
    if (lid == 0) smem[wid] = s;
    __syncthreads();

    if (t == 0) {
        float tot = 0.0f;
        #pragma unroll
        for (int i = 0; i < THREADS / 32; i++) tot += smem[i];
        g_partials[bid] = tot;   // fixed slot -> deterministic
    }
}

__global__ void dncm_final_kernel(const float* __restrict__ T,
                                  const float* __restrict__ P,
                                  const float* __restrict__ Q,
                                  float* __restrict__ out) {
    const int b = threadIdx.x;
    if (b >= BS) return;

    // r[j] = sum_c Q[j,c]   (Q row-major (16,3))
    float r[KDIM];
    #pragma unroll
    for (int j = 0; j < KDIM; j++)
        r[j] = Q[j * 3 + 0] + Q[j * 3 + 1] + Q[j * 3 + 2];

    // u[k] = sum_j T_b[k,j] * r[j]   (T_b row-major (16,16))
    const float* __restrict__ Tm = T + b * (KDIM * KDIM);
    float u[KDIM];
    #pragma unroll
    for (int k = 0; k < KDIM; k++) {
        float s = 0.0f;
        #pragma unroll
        for (int j = 0; j < KDIM; j++)
            s = fmaf(Tm[k * KDIM + j], r[j], s);
        u[k] = s;
    }

    // out[b] = (1/(HW*3)) * sum_{c0} w[c0] * S[b,c0],  w[c0] = sum_k P[c0,k]*u[k]
    float acc = 0.0f;
    #pragma unroll
    for (int c0 = 0; c0 < CHANS; c0++) {
        float w = 0.0f;
        #pragma unroll
        for (int k = 0; k < KDIM; k++)
            w = fmaf(P[c0 * KDIM + k], u[k], w);

        const float* __restrict__ p = g_partials + (b * CHANS + c0) * PARTS;
        float S = 0.0f;
        #pragma unroll
        for (int i = 0; i < PARTS; i++) S += p[i];

        acc = fmaf(w, S, acc);
    }
    out[b] = acc * (1.0f / (float)(HW * CHANS));
}

extern "C" void kernel_launch(void* const* d_in, const int* in_sizes, int n_in,
                              void* d_out, int out_size) {
    const float* I = (const float*)d_in[0];   // (16,3,512,512)
    const float* T = (const float*)d_in[1];   // (16,256)
    const float* P = (const float*)d_in[2];   // (3,16)
    const float* Q = (const float*)d_in[3];   // (16,3)
    float* out = (float*)d_out;               // (16,1)

    dncm_reduce_kernel<<<NCH * PARTS, THREADS>>>(I);
    dncm_final_kernel<<<1, 32>>>(T, P, Q, out);
}

// round 2
// speedup vs baseline: 1.3952x; 1.3952x over previous
#include <cuda_runtime.h>

// Fixed shapes: I(16,3,512,512), T(16,256), P(3,16), Q(16,3)
#define BS        16
#define CHANS     3
#define HW        (512 * 512)        // 262144 elems per channel
#define NCH       (BS * CHANS)       // 48 channel slabs
#define PARTS     64                 // partial sums per channel
#define CHUNK     (HW / PARTS)       // 4096 floats per block
#define THREADS   256
#define KDIM      16

// Deterministic scratch: fixed write slots, no atomics.
__device__ float g_partials[NCH * PARTS];

__global__ __launch_bounds__(THREADS)
void dncm_reduce_kernel(const float* __restrict__ I) {
    const int bid  = blockIdx.x;          // 0 .. NCH*PARTS-1
    const int ch   = bid >> 6;            // / PARTS
    const int part = bid & (PARTS - 1);

    const float4* __restrict__ base =
        reinterpret_cast<const float4*>(I + (size_t)ch * HW + (size_t)part * CHUNK);

    const int t = threadIdx.x;
    // 1024 float4 per block / 256 threads -> 4 independent vector loads (MLP=4, front-batched)
    float4 a = base[t];
    float4 b = base[t + 256];
    float4 c = base[t + 512];
    float4 d = base[t + 768];

    float s = ((a.x + a.y) + (a.z + a.w))
            + ((b.x + b.y) + (b.z + b.w))
            + ((c.x + c.y) + (c.z + c.w))
            + ((d.x + d.y) + (d.z + d.w));

    #pragma unroll
    for (int off = 16; off > 0; off >>= 1)
        s += __shfl_xor_sync(0xffffffffu, s, off);

    __shared__ float smem[THREADS / 32];
    const int wid = t >> 5;
    const int lid = t & 31;
    if (lid == 0) smem[wid] = s;
    __syncthreads();

    if (t == 0) {
        float tot = 0.0f;
        #pragma unroll
        for (int i = 0; i < THREADS / 32; i++) tot += smem[i];
        g_partials[bid] = tot;   // fixed slot -> deterministic
    }
}

// Second stage: 768 threads = 48 channels x 16 lanes.
// All 3072 partial loads issue in parallel (one DRAM round trip), then
// 16-lane shfl tree per channel, then 16 threads do the tiny matrix math.
__global__ __launch_bounds__(768)
void dncm_final_kernel(const float* __restrict__ T,
                       const float* __restrict__ P,
                       const float* __restrict__ Q,
                       float* __restrict__ out) {
    const int t  = threadIdx.x;        // 0..767
    const int ch = t >> 4;             // 0..47
    const int j  = t & 15;             // lane within channel team

    const float* __restrict__ p = g_partials + ch * PARTS;
    // 4 independent loads per thread
    float s = (p[j] + p[j + 16]) + (p[j + 32] + p[j + 48]);

    // reduce across the 16-lane team (xor offsets stay within the group)
    #pragma unroll
    for (int off = 8; off > 0; off >>= 1)
        s += __shfl_xor_sync(0xffffffffu, s, off);

    __shared__ float S[NCH];
    if (j == 0) S[ch] = s;
    __syncthreads();

    if (t < BS) {
        const int b = t;
        // r[j] = sum_c Q[j,c]
        float r[KDIM];
        #pragma unroll
        for (int k = 0; k < KDIM; k++)
            r[k] = Q[k * 3 + 0] + Q[k * 3 + 1] + Q[k * 3 + 2];

        // u[k] = sum_j T_b[k,j] * r[j]
        const float* __restrict__ Tm = T + b * (KDIM * KDIM);
        float u[KDIM];
        #pragma unroll
        for (int k = 0; k < KDIM; k++) {
            float acc = 0.0f;
            #pragma unroll
            for (int q = 0; q < KDIM; q++)
                acc = fmaf(Tm[k * KDIM + q], r[q], acc);
            u[k] = acc;
        }

        // out[b] = (1/(HW*3)) * sum_{c0} (P[c0,:]·u) * S[b,c0]
        float acc = 0.0f;
        #pragma unroll
        for (int c0 = 0; c0 < CHANS; c0++) {
            float w = 0.0f;
            #pragma unroll
            for (int k = 0; k < KDIM; k++)
                w = fmaf(P[c0 * KDIM + k], u[k], w);
            acc = fmaf(w, S[b * CHANS + c0], acc);
        }
        out[b] = acc * (1.0f / (float)(HW * CHANS));
    }
}

extern "C" void kernel_launch(void* const* d_in, const int* in_sizes, int n_in,
                              void* d_out, int out_size) {
    const float* I = (const float*)d_in[0];   // (16,3,512,512)
    const float* T = (const float*)d_in[1];   // (16,256)
    const float* P = (const float*)d_in[2];   // (3,16)
    const float* Q = (const float*)d_in[3];   // (16,3)
    float* out = (float*)d_out;               // (16,1)

    dncm_reduce_kernel<<<NCH * PARTS, THREADS>>>(I);
    dncm_final_kernel<<<1, 768>>>(T, P, Q, out);
}

// round 3
// speedup vs baseline: 1.8405x; 1.3191x over previous
#include <cuda_runtime.h>

// Fixed shapes: I(16,3,512,512), T(16,256), P(3,16), Q(16,3)
#define BS        16
#define CHANS     3
#define HW        (512 * 512)        // 262144 elems per channel
#define NCH       (BS * CHANS)       // 48 channel slabs
#define PARTS     64                 // partial sums per channel
#define CHUNK     (HW / PARTS)       // 4096 floats per block
#define THREADS   256
#define KDIM      16

// Deterministic scratch: fixed write slots, no atomics.
__device__ float g_partials[NCH * PARTS];

__global__ __launch_bounds__(THREADS)
void dncm_reduce_kernel(const float* __restrict__ I) {
    const int bid  = blockIdx.x;          // 0 .. NCH*PARTS-1
    const int ch   = bid >> 6;            // / PARTS
    const int part = bid & (PARTS - 1);

    const float4* __restrict__ base =
        reinterpret_cast<const float4*>(I + (size_t)ch * HW + (size_t)part * CHUNK);

    const int t = threadIdx.x;
    // 1024 float4 per block / 256 threads -> 4 independent vector loads (MLP=4)
    float4 a = base[t];
    float4 b = base[t + 256];
    float4 c = base[t + 512];
    float4 d = base[t + 768];

    float s = ((a.x + a.y) + (a.z + a.w))
            + ((b.x + b.y) + (b.z + b.w))
            + ((c.x + c.y) + (c.z + c.w))
            + ((d.x + d.y) + (d.z + d.w));

    #pragma unroll
    for (int off = 16; off > 0; off >>= 1)
        s += __shfl_xor_sync(0xffffffffu, s, off);

    __shared__ float smem[THREADS / 32];
    const int wid = t >> 5;
    const int lid = t & 31;
    if (lid == 0) smem[wid] = s;
    __syncthreads();

    if (t == 0) {
        float tot = 0.0f;
        #pragma unroll
        for (int i = 0; i < THREADS / 32; i++) tot += smem[i];
        g_partials[bid] = tot;   // fixed slot -> deterministic
    }
}

// Final stage, one block of 768 threads.
//   Phase 1 (all 768): channel teams of 16 lanes reduce the 3072 partials -> S[48].
//   Phase 2 (threads 0..255): thread (b,k) = (t>>4, t&15) computes
//       (T_b[k,:] . r) * A[b,k],   r[j] = sum_c Q[j,c],  A[b,k] = sum_c S[b,c]*P[c,k]
//   then a 16-lane shfl reduce over k yields out[b].
// All global loads (partials, T via float4, Q/P broadcasts) are independent
// and issue together -> a couple of DRAM round trips total.
__global__ __launch_bounds__(768)
void dncm_final_kernel(const float* __restrict__ T,
                       const float* __restrict__ P,
                       const float* __restrict__ Q,
                       float* __restrict__ out) {
    const int t  = threadIdx.x;        // 0..767
    const int ch = t >> 4;             // 0..47
    const int j  = t & 15;             // lane within team

    // -- partial loads (all threads) --
    const float* __restrict__ p = g_partials + ch * PARTS;
    float s = (p[j] + p[j + 16]) + (p[j + 32] + p[j + 48]);

    // -- T row + r computation (threads 0..255), loads overlap with the above --
    const int b = t >> 4;              // batch   (valid when t < 256)
    const int k = t & 15;              // k index
    float4 t0, t1, t2, t3;
    float r[KDIM];
    if (t < 256) {
        const float4* __restrict__ Tv =
            reinterpret_cast<const float4*>(T + b * (KDIM * KDIM) + k * KDIM);
        t0 = Tv[0]; t1 = Tv[1]; t2 = Tv[2]; t3 = Tv[3];
        #pragma unroll
        for (int q = 0; q < KDIM; q++)
            r[q] = Q[q * 3 + 0] + Q[q * 3 + 1] + Q[q * 3 + 2];  // broadcast loads
    }

    // -- reduce partials within 16-lane teams --
    #pragma unroll
    for (int off = 8; off > 0; off >>= 1)
        s += __shfl_xor_sync(0xffffffffu, s, off);

    __shared__ float S[NCH];
    if (j == 0) S[ch] = s;
    __syncthreads();

    if (t < 256) {
        // A[b,k] = sum_c S[b,c] * P[c,k]
        const float A = S[b * CHANS + 0] * P[0 * KDIM + k]
                      + S[b * CHANS + 1] * P[1 * KDIM + k]
                      + S[b * CHANS + 2] * P[2 * KDIM + k];

        // d = T_b[k,:] . r
        float d = t0.x * r[0] + t0.y * r[1] + t0.z * r[2]  + t0.w * r[3]
                + t1.x * r[4] + t1.y * r[5] + t1.z * r[6]  + t1.w * r[7]
                + t2.x * r[8] + t2.y * r[9] + t2.z * r[10] + t2.w * r[11]
                + t3.x * r[12]+ t3.y * r[13]+ t3.z * r[14] + t3.w * r[15];

        float val = d * A;
        #pragma unroll
        for (int off = 8; off > 0; off >>= 1)
            val += __shfl_xor_sync(0xffffffffu, val, off);

        if (k == 0)
            out[b] = val * (1.0f / (float)(HW * CHANS));
    }
}

extern "C" void kernel_launch(void* const* d_in, const int* in_sizes, int n_in,
                              void* d_out, int out_size) {
    const float* I = (const float*)d_in[0];   // (16,3,512,512)
    const float* T = (const float*)d_in[1];   // (16,256)
    const float* P = (const float*)d_in[2];   // (3,16)
    const float* Q = (const float*)d_in[3];   // (16,3)
    float* out = (float*)d_out;               // (16,1)

    dncm_reduce_kernel<<<NCH * PARTS, THREADS>>>(I);
    dncm_final_kernel<<<1, 768>>>(T, P, Q, out);
}